// round 15
// baseline (speedup 1.0000x reference)
#include <cuda_runtime.h>
#include <math.h>
#include <stdint.h>

#define B_    4096
#define T_    16
#define D_    256
#define L_    4
#define KIN_  1056
#define EPS_  1e-4f
#define M_BIG (B_ * T_)          // 65536

// ---------------- scratch ----------------
__device__ float g_tokA[M_BIG * D_];
__device__ float g_tokB[M_BIG * D_];
__device__ float g_states[M_BIG * D_];
__device__ float g_part[2][8 * M_BIG];   // per-n32 partial sum-of-squares (8 slots)
__device__ float g_Wi[L_ * D_ * D_];     // rna(W_in  * nw)
__device__ float g_Wo[L_ * D_ * D_];     // rna(W_out)
__device__ float g_Ws[L_ * D_ * D_];     // rna(W_skip * nw)
__device__ float g_W0r[D_ * KIN_];       // rna(W0)

// ---------------- PTX helpers ----------------
__device__ __forceinline__ uint32_t smem_u32(const void* p) {
    uint32_t a;
    asm("{ .reg .u64 t; cvta.to.shared.u64 t, %1; cvt.u32.u64 %0, t; }" : "=r"(a) : "l"(p));
    return a;
}
__device__ __forceinline__ uint32_t f2tf32(float x) {
    uint32_t r; asm("cvt.rna.tf32.f32 %0, %1;" : "=r"(r) : "f"(x)); return r;
}
__device__ __forceinline__ float rna(float x) { return __uint_as_float(f2tf32(x)); }

__device__ __forceinline__ void mma_tf32(float* c, const uint32_t* a, const uint32_t* b) {
    asm volatile(
        "mma.sync.aligned.m16n8k8.row.col.f32.tf32.tf32.f32 "
        "{%0,%1,%2,%3}, {%4,%5,%6,%7}, {%8,%9}, {%0,%1,%2,%3};"
        : "+f"(c[0]), "+f"(c[1]), "+f"(c[2]), "+f"(c[3])
        : "r"(a[0]), "r"(a[1]), "r"(a[2]), "r"(a[3]), "r"(b[0]), "r"(b[1]));
}
__device__ __forceinline__ void ldsm4(uint32_t* r, uint32_t addr) {
    asm volatile("ldmatrix.sync.aligned.m8n8.x4.shared.b16 {%0,%1,%2,%3}, [%4];"
                 : "=r"(r[0]), "=r"(r[1]), "=r"(r[2]), "=r"(r[3]) : "r"(addr));
}
__device__ __forceinline__ void cp16(uint32_t s, const float* g) {
    asm volatile("{ .reg .u64 gp; cvta.to.global.u64 gp, %1;\n\t"
                 "cp.async.cg.shared.global [%0], [gp], 16; }"
                 :: "r"(s), "l"(g) : "memory");
}
__device__ __forceinline__ void cp_commit() { asm volatile("cp.async.commit_group;" ::: "memory"); }
__device__ __forceinline__ void cp_wait0()  { asm volatile("cp.async.wait_group 0;" ::: "memory"); }
__device__ __forceinline__ void cp_wait1()  { asm volatile("cp.async.wait_group 1;" ::: "memory"); }
#define BARP(id) asm volatile("bar.sync %0, 64;" :: "r"(id) : "memory")

__device__ __forceinline__ float part_scale(const float* pin, int m) {
    float s = 0.f;
#pragma unroll
    for (int q = 0; q < 8; q++) s += pin[q * M_BIG + m];
    return rsqrtf(s * (1.0f / 256.0f) + EPS_);
}

// swizzled A-buffer: 32 rows x 128B, col XOR (row&7)<<4 -> conflict-free, no padding
__device__ __forceinline__ uint32_t swz(int row, int bcol) {
    return (uint32_t)(row * 128 + (bcol ^ ((row & 7) << 4)));
}
#define AC4    4096              // swizzled A chunk bytes
#define ACHUNK 4608              // padded pitch chunk (k_proj only)

// pair-shared A staging into swizzled buffer
__device__ __forceinline__ void stage_pair(uint32_t dst, const float* Agrp, int k0, int nh) {
    int lane = threadIdx.x & 31;
    int row  = nh * 16 + (lane >> 1);
    int part = lane & 1;
    const float* p = Agrp + (size_t)row * 256 + k0 + part * 16;
#pragma unroll
    for (int j = 0; j < 4; j++)
        cp16(dst + swz(row, part * 64 + j * 16), p + j * 4);
}

// =========== GEMM1 + fused scan: 512 thr, 8 groups, BN=128, grid.y=2, 3 A bufs ===========
#define G1_WB    133120
#define G1_REG   (3 * AC4)                 // 12288
#define SM1_TOT  (G1_WB + 8 * G1_REG)      // 231424
__global__ __launch_bounds__(512, 1)
void k_gemm_scan(const float* __restrict__ P, const float* __restrict__ Wi,
                 const float* __restrict__ bi, const float* __restrict__ ld_,
                 const float* __restrict__ partIn, float* __restrict__ states)
{
    extern __shared__ float smf[];
    uint32_t sm32 = smem_u32(smf);
    const int tid = threadIdx.x, lane = tid & 31, w = tid >> 5;
    const int grp = w >> 1, nh = w & 1, bid = grp + 1;
    const int lr = lane & 7, lb8 = (lane >> 3) & 1, lb16 = (lane >> 4) & 1;
    const int gid = lane >> 2, tig = lane & 3;
    const int qb = blockIdx.y * 128;

    // persistent W half (128 n-rows x 256 k), pitch 1040B
    {
        int r = tid >> 2, seg = tid & 3;
        const float* s = Wi + (size_t)(qb + r) * 256 + seg * 64;
        uint32_t d = sm32 + r * 1040 + seg * 256;
#pragma unroll
        for (int j = 0; j < 16; j++) cp16(d + j * 16, s + j * 4);
    }
    cp_commit(); cp_wait0();
    __syncthreads();

    const uint32_t AB = sm32 + G1_WB + grp * G1_REG;
    float* ABf = smf + (G1_WB / 4) + grp * (G1_REG / 4);

    for (int tile = blockIdx.x; tile < M_BIG / 256; tile += gridDim.x) {
        const int m0g = tile * 256 + grp * 32;
        const float* Am = P + (size_t)m0g * 256;

        stage_pair(AB,       Am, 0,  nh); cp_commit();
        stage_pair(AB + AC4, Am, 32, nh); cp_commit();

        float acc[2][8][4];
#pragma unroll
        for (int mt = 0; mt < 2; mt++)
#pragma unroll
            for (int j = 0; j < 8; j++)
#pragma unroll
                for (int q = 0; q < 4; q++) acc[mt][j][q] = 0.f;

#pragma unroll 1
        for (int c = 0; c < 8; c++) {
            cp_wait1();
            BARP(bid);
            if (c + 2 < 8) stage_pair(AB + ((c + 2) % 3) * AC4, Am, (c + 2) * 32, nh);
            cp_commit();
            const uint32_t A0 = AB + (c % 3) * AC4;
#pragma unroll
            for (int ks = 0; ks < 4; ks++) {
                const int colb = lb16 * 16 + ks * 32;
                uint32_t a[2][4];
                ldsm4(a[0], A0 + swz(lr + lb8 * 8, colb));
                ldsm4(a[1], A0 + swz(lr + lb8 * 8, colb) + 2048);
#pragma unroll
                for (int ng = 0; ng < 4; ng++) {
                    uint32_t bf[4];
                    ldsm4(bf, sm32 + (nh * 64 + ng * 16 + lr + lb16 * 8) * 1040
                              + lb8 * 16 + (c * 32 + ks * 8) * 4);
                    mma_tf32(acc[0][ng * 2],     a[0], &bf[0]);
                    mma_tf32(acc[0][ng * 2 + 1], a[0], &bf[2]);
                    mma_tf32(acc[1][ng * 2],     a[1], &bf[0]);
                    mma_tf32(acc[1][ng * 2 + 1], a[1], &bf[2]);
                }
            }
        }
        BARP(bid);

        // warp-local epilogue: Uw 16x64 + sc 16 in own slice
        float* Uw = ABf + nh * 1536;
#pragma unroll
        for (int mt = 0; mt < 2; mt++) {
#pragma unroll
            for (int j = 0; j < 8; j++) {
                int col = j * 8 + tig * 2;
                Uw[gid * 64 + col]           = acc[mt][j][0];
                Uw[gid * 64 + col + 1]       = acc[mt][j][1];
                Uw[(gid + 8) * 64 + col]     = acc[mt][j][2];
                Uw[(gid + 8) * 64 + col + 1] = acc[mt][j][3];
            }
            if (lane < 16) Uw[1024 + lane] = part_scale(partIn, m0g + mt * 16 + lane);
            __syncwarp();
#pragma unroll
            for (int q = 0; q < 2; q++) {
                int cc = lane + 32 * q;
                int gc = qb + nh * 64 + cc;
                float dec = 1.0f / (1.0f + expf(-ld_[gc]));
                float bias = bi[gc];
                float st = 0.f;
#pragma unroll
                for (int tt = 0; tt < 16; tt++) {
                    float u = Uw[tt * 64 + cc] * Uw[1024 + tt] + bias;
                    st = dec * st + u;
                    Uw[tt * 64 + cc] = st;
                }
            }
            __syncwarp();
#pragma unroll
            for (int i = 0; i < 8; i++) {
                int f = lane + 32 * i;
                int row = f >> 4, c4 = (f & 15) * 4;
                float4 v = *(float4*)&Uw[row * 64 + c4];
                *(float4*)&states[(size_t)(m0g + mt * 16 + row) * 256
                                  + qb + nh * 64 + c4] = v;
            }
            __syncwarp();
        }
        BARP(bid);
    }
}

// =========== GEMM2: 512 thr, 8 pair-groups, BN=64, K=512 ([Ws;Wo]), 3 A bufs ===========
#define G2_WB    132096
#define G2_REG   (3 * AC4)
#define SM2_TOT  (G2_WB + 8 * G2_REG)      // 230400
__global__ __launch_bounds__(512, 1)
void k_gemm2(const float* __restrict__ P, const float* __restrict__ Wsp,
             const float* __restrict__ states, const float* __restrict__ Wo,
             const float* __restrict__ partIn,
             const float* __restrict__ bo, const float* __restrict__ bsk,
             float* __restrict__ Q, float* __restrict__ partOut)
{
    extern __shared__ float smf[];
    uint32_t sm32 = smem_u32(smf);
    const int tid = threadIdx.x, lane = tid & 31, w = tid >> 5;
    const int grp = w >> 1, nh = w & 1, bid = grp + 1;
    const int lr = lane & 7, lb8 = (lane >> 3) & 1, lb16 = (lane >> 4) & 1;
    const int gid = lane >> 2, tig = lane & 3;
    const int qb = blockIdx.y * 64;

    // persistent [Ws | Wo] quarter (64 n-rows x 512 k), pitch 2064B
    {
        int r = tid >> 3, seg = tid & 7;
        int col64 = seg * 64;
        const float* s = (col64 < 256) ? (Wsp + (size_t)(qb + r) * 256 + col64)
                                       : (Wo  + (size_t)(qb + r) * 256 + col64 - 256);
        uint32_t d = sm32 + r * 2064 + col64 * 4;
#pragma unroll
        for (int j = 0; j < 16; j++) cp16(d + j * 16, s + j * 4);
    }
    cp_commit(); cp_wait0();
    __syncthreads();

    const uint32_t AB = sm32 + G2_WB + grp * G2_REG;
    float* ABf = smf + (G2_WB / 4) + grp * (G2_REG / 4);

    for (int tile = blockIdx.x; tile < M_BIG / 256; tile += gridDim.x) {
        const int m0g = tile * 256 + grp * 32;
        const float* Pm = P + (size_t)m0g * 256;
        const float* Sm = states + (size_t)m0g * 256;

        stage_pair(AB,       Pm, 0,  nh); cp_commit();
        stage_pair(AB + AC4, Pm, 32, nh); cp_commit();

        float acc[2][4][4];
#pragma unroll
        for (int mt = 0; mt < 2; mt++)
#pragma unroll
            for (int j = 0; j < 4; j++)
#pragma unroll
                for (int q = 0; q < 4; q++) acc[mt][j][q] = 0.f;

#pragma unroll 1
        for (int c = 0; c < 16; c++) {
            cp_wait1();
            BARP(bid);
            if (c + 2 < 16) {
                int cn = c + 2;
                stage_pair(AB + (cn % 3) * AC4, cn < 8 ? Pm : Sm, (cn & 7) * 32, nh);
            }
            cp_commit();
            if (c == 8) {
                // finished x@Ws' half: apply rmsnorm row scales to acc
#pragma unroll
                for (int mt = 0; mt < 2; mt++) {
                    float s0 = part_scale(partIn, m0g + mt * 16 + gid);
                    float s1 = part_scale(partIn, m0g + mt * 16 + gid + 8);
#pragma unroll
                    for (int j = 0; j < 4; j++) {
                        acc[mt][j][0] *= s0; acc[mt][j][1] *= s0;
                        acc[mt][j][2] *= s1; acc[mt][j][3] *= s1;
                    }
                }
            }
            const uint32_t A0 = AB + (c % 3) * AC4;
            // batch all A-fragment LDSMs for the chunk (MLP burst)
            uint32_t afr[4][2][4];
#pragma unroll
            for (int ks = 0; ks < 4; ks++) {
                const int colb = lb16 * 16 + ks * 32;
                ldsm4(afr[ks][0], A0 + swz(lr + lb8 * 8, colb));
                ldsm4(afr[ks][1], A0 + swz(lr + lb8 * 8, colb) + 2048);
            }
#pragma unroll
            for (int ks = 0; ks < 4; ks++) {
#pragma unroll
                for (int ng = 0; ng < 2; ng++) {
                    uint32_t bf[4];
                    ldsm4(bf, sm32 + (nh * 32 + ng * 16 + lr + lb16 * 8) * 2064
                              + lb8 * 16 + (c * 32 + ks * 8) * 4);
                    mma_tf32(acc[0][ng * 2],     afr[ks][0], &bf[0]);
                    mma_tf32(acc[0][ng * 2 + 1], afr[ks][0], &bf[2]);
                    mma_tf32(acc[1][ng * 2],     afr[ks][1], &bf[0]);
                    mma_tf32(acc[1][ng * 2 + 1], afr[ks][1], &bf[2]);
                }
            }
        }
        BARP(bid);   // pair done computing before Uw overwrites buffers

        // warp-local epilogue: Uw 32 rows x 32 cols (own n32 slice)
        float* Uw = ABf + nh * 1024;
#pragma unroll
        for (int mt = 0; mt < 2; mt++) {
            int r = mt * 16 + gid;
#pragma unroll
            for (int j = 0; j < 4; j++) {
                int lc = j * 8 + tig * 2;
                int gc = qb + nh * 32 + lc;
                float bb0 = bo[gc]     + bsk[gc];
                float bb1 = bo[gc + 1] + bsk[gc + 1];
                Uw[r * 32 + lc]           = acc[mt][j][0] + bb0;
                Uw[r * 32 + lc + 1]       = acc[mt][j][1] + bb1;
                Uw[(r + 8) * 32 + lc]     = acc[mt][j][2] + bb0;
                Uw[(r + 8) * 32 + lc + 1] = acc[mt][j][3] + bb1;
            }
        }
        __syncwarp();
        // residual + store + per-row sumsq over own n32
#pragma unroll
        for (int i = 0; i < 8; i++) {
            int f = lane + 32 * i;
            int row = f >> 3, c4 = (f & 7) * 4;
            float4 v = *(float4*)&Uw[row * 32 + c4];
            float4 p = *(const float4*)&Pm[(size_t)row * 256 + qb + nh * 32 + c4];
            v.x += p.x; v.y += p.y; v.z += p.z; v.w += p.w;
            *(float4*)&Q[(size_t)(m0g + row) * 256 + qb + nh * 32 + c4] = v;
            float s = v.x * v.x + v.y * v.y + v.z * v.z + v.w * v.w;
            s += __shfl_xor_sync(0xffffffffu, s, 1);
            s += __shfl_xor_sync(0xffffffffu, s, 2);
            s += __shfl_xor_sync(0xffffffffu, s, 4);
            if ((lane & 7) == 0)
                partOut[(size_t)(blockIdx.y * 2 + nh) * M_BIG + m0g + row] = s;
        }
        __syncwarp();
        BARP(bid);   // partner epilogue done before next tile staging
    }
}

// =========== prologue / small kernels ===========
__global__ void prep_weights(const float* __restrict__ Wi, const float* __restrict__ Wo,
                             const float* __restrict__ Wsk, const float* __restrict__ nw,
                             const float* __restrict__ W0)
{
    int i = blockIdx.x * blockDim.x + threadIdx.x;
    if (i < L_ * D_ * D_) {
        int l = i >> 16, k = i & 255;
        float w = nw[l * D_ + k];
        g_Wi[i] = rna(Wi[i] * w);
        g_Ws[i] = rna(Wsk[i] * w);
        g_Wo[i] = rna(Wo[i]);
    }
    if (i < D_ * KIN_) g_W0r[i] = rna(W0[i]);
}

__global__ void shift_scale_kernel(const float* __restrict__ deter,
                                   float* __restrict__ tok, float* __restrict__ part0)
{
    int gw = (blockIdx.x * blockDim.x + threadIdx.x) >> 5;
    if (gw >= B_ * 15) return;
    int lane = threadIdx.x & 31;
    int b = gw / 15, t = gw - b * 15;
    const float4* src = (const float4*)(deter + (size_t)b * 4096 + (t + 1) * 256) + lane;
    float4* dst = (float4*)(tok + (size_t)b * 4096 + t * 256) + lane;
    float4 v0 = src[0], v1 = src[32];
    dst[0] = v0; dst[32] = v1;
    float s = v0.x*v0.x + v0.y*v0.y + v0.z*v0.z + v0.w*v0.w
            + v1.x*v1.x + v1.y*v1.y + v1.z*v1.z + v1.w*v1.w;
#pragma unroll
    for (int o = 16; o > 0; o >>= 1) s += __shfl_xor_sync(0xffffffffu, s, o);
    if (lane == 0) {
        int mm = b * 16 + t;
        part0[mm] = s;
#pragma unroll
        for (int q = 1; q < 8; q++) part0[q * M_BIG + mm] = 0.f;
    }
}

__global__ void apply_norm_kernel(const float* __restrict__ in, const float* __restrict__ w,
                                  float* __restrict__ out)
{
    int gw = (blockIdx.x * blockDim.x + threadIdx.x) >> 5;
    int lane = threadIdx.x & 31;
    const float* rp = in + (size_t)gw * 256 + lane * 8;
    float v[8];
    *(float4*)&v[0] = *(const float4*)rp;
    *(float4*)&v[4] = *(const float4*)(rp + 4);
    float s = 0.f;
#pragma unroll
    for (int j = 0; j < 8; j++) s += v[j] * v[j];
#pragma unroll
    for (int o = 16; o > 0; o >>= 1) s += __shfl_xor_sync(0xffffffffu, s, o);
    float sc = rsqrtf(s * (1.0f / 256.0f) + EPS_);
    float wl[8];
    *(float4*)&wl[0] = *(const float4*)(w + lane * 8);
    *(float4*)&wl[4] = *(const float4*)(w + lane * 8 + 4);
    float o8[8];
#pragma unroll
    for (int j = 0; j < 8; j++) o8[j] = v[j] * sc * wl[j];
    float* op = out + (size_t)gw * 256 + lane * 8;
    *(float4*)op = *(float4*)&o8[0];
    *(float4*)(op + 4) = *(float4*)&o8[4];
}

// =========== input proj: BM=32, 128 CTAs, 3 bufs, 1 sync/chunk, fused concat ===========
#define KPB_B    13824
#define SMP_TOT  124416

__device__ __forceinline__ void kp_stageA(uint32_t sm32, int buf,
                                          const float* stoch, int m0, int c)
{
    const int tid = threadIdx.x;
    int row = tid >> 3, kc = (tid & 7) * 4;
    cp16(sm32 + buf * ACHUNK + row * 144 + kc * 4,
         stoch + (size_t)(m0 + row) * 1024 + c * 32 + kc);
}

__device__ __forceinline__ void kp_stageB(uint32_t sm32, int buf, int c)
{
    const int tid = threadIdx.x;
    const float* p = g_W0r + (size_t)tid * KIN_ + c * 32;
    uint32_t d = sm32 + KPB_B + buf * 36864 + tid * 144;
#pragma unroll
    for (int j = 0; j < 8; j++) cp16(d + j * 16, p + j * 4);
}

__global__ __launch_bounds__(256)
void k_proj(const float* __restrict__ stoch, const float* __restrict__ action,
            const float* __restrict__ b0, const float* __restrict__ g0,
            float* __restrict__ tokA, float* __restrict__ part0)
{
    extern __shared__ float smf[];
    uint32_t sm32 = smem_u32(smf);
    const int tid = threadIdx.x, wid = tid >> 5, lane = tid & 31;
    const int wm = wid & 1, wn = wid >> 1;
    const int gid = lane >> 2, tig = lane & 3;
    const int lr = lane & 7, lb8 = (lane >> 3) & 1, lb16 = (lane >> 4) & 1;
    const int m0 = blockIdx.x * 32;

    const uint32_t aoff = (uint32_t)(wm * 16 + lr + lb8 * 8) * 144 + lb16 * 16;
    const uint32_t boff = (uint32_t)(wn * 64 + lr + lb16 * 8) * 144 + lb8 * 16;

    float acc[8][4];
#pragma unroll
    for (int j = 0; j < 8; j++)
#pragma unroll
        for (int q = 0; q < 4; q++) acc[j][q] = 0.f;

    kp_stageA(sm32, 0, stoch, m0, 0); kp_stageB(sm32, 0, 0); cp_commit();
    kp_stageA(sm32, 1, stoch, m0, 1); kp_stageB(sm32, 1, 1); cp_commit();

#pragma unroll 1
    for (int c = 0; c < 33; c++) {
        if (c == 32) cp_wait0(); else cp_wait1();
        __syncthreads();
        int cn = c + 2;
        if (cn < 33) {
            int buf = cn % 3;
            if (cn == 32) {
                int row = tid >> 3, kc = (tid & 7) * 4;
                const float* p = action + (size_t)(m0 + row) * 32 + kc;
                float4 v = *(const float4*)p;
                v.x /= fmaxf(fabsf(v.x), 1.0f);
                v.y /= fmaxf(fabsf(v.y), 1.0f);
                v.z /= fmaxf(fabsf(v.z), 1.0f);
                v.w /= fmaxf(fabsf(v.w), 1.0f);
                *(float4*)((char*)smf + buf * ACHUNK + row * 144 + kc * 4) = v;
                kp_stageB(sm32, buf, cn);
            } else {
                kp_stageA(sm32, buf, stoch, m0, cn);
                kp_stageB(sm32, buf, cn);
            }
        }
        cp_commit();
        const uint32_t sA = sm32 + (c % 3) * ACHUNK;
        const uint32_t sB = sm32 + KPB_B + (c % 3) * 36864;
#pragma unroll
        for (int ks = 0; ks < 4; ks++) {
            uint32_t a0[4], bf[4][4];
            ldsm4(a0, sA + aoff + ks * 32);
#pragma unroll
            for (int pr = 0; pr < 4; pr++)
                ldsm4(bf[pr], sB + boff + pr * 2304 + ks * 32);
#pragma unroll
            for (int pr = 0; pr < 4; pr++) {
                mma_tf32(acc[2*pr],   a0, &bf[pr][0]);
                mma_tf32(acc[2*pr+1], a0, &bf[pr][2]);
            }
        }
    }
    __syncthreads();

    float* Us = smf;   // [32][260]
#pragma unroll
    for (int j = 0; j < 8; j++) {
        int r = wm * 16 + gid;
        int col = wn * 64 + j * 8 + tig * 2;
        Us[r * 260 + col]           = acc[j][0];
        Us[r * 260 + col + 1]       = acc[j][1];
        Us[(r + 8) * 260 + col]     = acc[j][2];
        Us[(r + 8) * 260 + col + 1] = acc[j][3];
    }
    __syncthreads();
#pragma unroll
    for (int k = 0; k < 4; k++) {
        int row = k * 8 + wid;
        int m = m0 + row;
        float v[8]; float sum = 0.f;
#pragma unroll
        for (int j = 0; j < 8; j++) {
            int c = lane + 32 * j;
            v[j] = Us[row * 260 + c] + b0[c];
            sum += v[j] * v[j];
        }
#pragma unroll
        for (int o = 16; o > 0; o >>= 1) sum += __shfl_xor_sync(0xffffffffu, sum, o);
        float sc = rsqrtf(sum * (1.0f / 256.0f) + EPS_);
        float s2 = 0.f;
#pragma unroll
        for (int j = 0; j < 8; j++) {
            int c = lane + 32 * j;
            float y = v[j] * sc * g0[c];
            y = y / (1.0f + expf(-y));
            s2 += y * y;
            tokA[(size_t)m * 4096 + 3840 + c] = y;
        }
#pragma unroll
        for (int o = 16; o > 0; o >>= 1) s2 += __shfl_xor_sync(0xffffffffu, s2, o);
        if (lane == 0) {
            int mm = m * 16 + 15;
            part0[mm] = s2;
#pragma unroll
            for (int q = 1; q < 8; q++) part0[q * M_BIG + mm] = 0.f;
        }
    }
}

// ---------------- launch ----------------
extern "C" void kernel_launch(void* const* d_in, const int* in_sizes, int n_in,
                              void* d_out, int out_size)
{
    const float* stoch      = (const float*)d_in[0];
    const float* deter      = (const float*)d_in[1];
    const float* action     = (const float*)d_in[2];
    const float* W0         = (const float*)d_in[3];
    const float* b0         = (const float*)d_in[4];
    const float* g0         = (const float*)d_in[5];
    const float* norm_w     = (const float*)d_in[6];
    const float* W_in       = (const float*)d_in[7];
    const float* b_in       = (const float*)d_in[8];
    const float* W_out      = (const float*)d_in[9];
    const float* b_out      = (const float*)d_in[10];
    const float* W_skip     = (const float*)d_in[11];
    const float* b_skip     = (const float*)d_in[12];
    const float* log_decay  = (const float*)d_in[13];
    const float* out_norm_w = (const float*)d_in[14];
    float* out = (float*)d_out;

    float *tokA, *tokB, *states, *part, *Wi_s, *Wo_s, *Ws_s;
    cudaGetSymbolAddress((void**)&tokA,   g_tokA);
    cudaGetSymbolAddress((void**)&tokB,   g_tokB);
    cudaGetSymbolAddress((void**)&states, g_states);
    cudaGetSymbolAddress((void**)&part,   g_part);
    cudaGetSymbolAddress((void**)&Wi_s,   g_Wi);
    cudaGetSymbolAddress((void**)&Wo_s,   g_Wo);
    cudaGetSymbolAddress((void**)&Ws_s,   g_Ws);

    cudaFuncSetAttribute(k_proj,      cudaFuncAttributeMaxDynamicSharedMemorySize, SMP_TOT);
    cudaFuncSetAttribute(k_gemm_scan, cudaFuncAttributeMaxDynamicSharedMemorySize, SM1_TOT);
    cudaFuncSetAttribute(k_gemm2,     cudaFuncAttributeMaxDynamicSharedMemorySize, SM2_TOT);

    prep_weights<<<(D_ * KIN_ + 255) / 256 + 1, 256>>>(W_in, W_out, W_skip, norm_w, W0);
    shift_scale_kernel<<<B_ * 15 / 8, 256>>>(deter, tokA, part);
    k_proj<<<B_ / 32, 256, SMP_TOT>>>(stoch, action, b0, g0, tokA, part);

    float* Pb = tokA;
    float* Qb = tokB;
    for (int l = 0; l < L_; l++) {
        const float* Wi  = Wi_s + (size_t)l * D_ * D_;
        const float* Wo  = Wo_s + (size_t)l * D_ * D_;
        const float* Ws  = Ws_s + (size_t)l * D_ * D_;
        const float* bi  = b_in      + (size_t)l * D_;
        const float* bo  = b_out     + (size_t)l * D_;
        const float* bsk = b_skip    + (size_t)l * D_;
        const float* ld  = log_decay + (size_t)l * D_;
        float* partIn  = part + (size_t)(l & 1) * 8 * M_BIG;
        float* partOut = part + (size_t)((l + 1) & 1) * 8 * M_BIG;

        k_gemm_scan<<<dim3(74, 2), 512, SM1_TOT>>>(Pb, Wi, bi, ld, partIn, states);
        k_gemm2<<<dim3(37, 4), 512, SM2_TOT>>>(Pb, Ws, states, Wo, partIn,
                                               bo, bsk, Qb, partOut);
        float* tmp = Pb; Pb = Qb; Qb = tmp;
    }

    apply_norm_kernel<<<M_BIG / 8, 256>>>(Pb, out_norm_w, out);
}

// round 16
// speedup vs baseline: 1.0122x; 1.0122x over previous
#include <cuda_runtime.h>
#include <math.h>
#include <stdint.h>

#define B_    4096
#define T_    16
#define D_    256
#define L_    4
#define KIN_  1056
#define EPS_  1e-4f
#define M_BIG (B_ * T_)          // 65536

// ---------------- scratch ----------------
__device__ float g_tokA[M_BIG * D_];
__device__ float g_tokB[M_BIG * D_];
__device__ float g_states[M_BIG * D_];
__device__ float g_part[2][4 * M_BIG];   // per-quarter partial sum-of-squares
__device__ float g_Wi[L_ * D_ * D_];     // rna(W_in  * nw)
__device__ float g_Wo[L_ * D_ * D_];     // rna(W_out)
__device__ float g_Ws[L_ * D_ * D_];     // rna(W_skip * nw)
__device__ float g_W0r[D_ * KIN_];       // rna(W0)

// ---------------- PTX helpers ----------------
__device__ __forceinline__ uint32_t smem_u32(const void* p) {
    uint32_t a;
    asm("{ .reg .u64 t; cvta.to.shared.u64 t, %1; cvt.u32.u64 %0, t; }" : "=r"(a) : "l"(p));
    return a;
}
__device__ __forceinline__ uint32_t f2tf32(float x) {
    uint32_t r; asm("cvt.rna.tf32.f32 %0, %1;" : "=r"(r) : "f"(x)); return r;
}
__device__ __forceinline__ float rna(float x) { return __uint_as_float(f2tf32(x)); }

__device__ __forceinline__ void mma_tf32(float* c, const uint32_t* a, const uint32_t* b) {
    asm volatile(
        "mma.sync.aligned.m16n8k8.row.col.f32.tf32.tf32.f32 "
        "{%0,%1,%2,%3}, {%4,%5,%6,%7}, {%8,%9}, {%0,%1,%2,%3};"
        : "+f"(c[0]), "+f"(c[1]), "+f"(c[2]), "+f"(c[3])
        : "r"(a[0]), "r"(a[1]), "r"(a[2]), "r"(a[3]), "r"(b[0]), "r"(b[1]));
}
__device__ __forceinline__ void ldsm4(uint32_t* r, uint32_t addr) {
    asm volatile("ldmatrix.sync.aligned.m8n8.x4.shared.b16 {%0,%1,%2,%3}, [%4];"
                 : "=r"(r[0]), "=r"(r[1]), "=r"(r[2]), "=r"(r[3]) : "r"(addr));
}
__device__ __forceinline__ void cp16(uint32_t s, const float* g) {
    asm volatile("{ .reg .u64 gp; cvta.to.global.u64 gp, %1;\n\t"
                 "cp.async.cg.shared.global [%0], [gp], 16; }"
                 :: "r"(s), "l"(g) : "memory");
}
__device__ __forceinline__ void cp_commit() { asm volatile("cp.async.commit_group;" ::: "memory"); }
__device__ __forceinline__ void cp_wait0()  { asm volatile("cp.async.wait_group 0;" ::: "memory"); }
__device__ __forceinline__ void cp_wait1()  { asm volatile("cp.async.wait_group 1;" ::: "memory"); }
#define BARP(id) asm volatile("bar.sync %0, 64;" :: "r"(id) : "memory")

__device__ __forceinline__ float part_scale(const float* pin, int m) {
    float s = pin[m] + pin[M_BIG + m] + pin[2 * M_BIG + m] + pin[3 * M_BIG + m];
    return rsqrtf(s * (1.0f / 256.0f) + EPS_);
}

// swizzled A-buffer: 32 rows x 128B, col XOR (row&7)<<4 -> conflict-free, no padding
__device__ __forceinline__ uint32_t swz(int row, int bcol) {
    return (uint32_t)(row * 128 + (bcol ^ ((row & 7) << 4)));
}
#define AC4    4096              // swizzled A chunk bytes
#define ACHUNK 4608              // padded pitch chunk (k_proj only)

// pair-shared A staging into swizzled buffer
__device__ __forceinline__ void stage_pair(uint32_t dst, const float* Agrp, int k0, int nh) {
    int lane = threadIdx.x & 31;
    int row  = nh * 16 + (lane >> 1);
    int part = lane & 1;
    const float* p = Agrp + (size_t)row * 256 + k0 + part * 16;
#pragma unroll
    for (int j = 0; j < 4; j++)
        cp16(dst + swz(row, part * 64 + j * 16), p + j * 4);
}

// =========== GEMM1 + fused scan: 512 thr, 8 groups, BN=128, grid.y=2, 3 A bufs ===========
#define G1_WB    133120
#define G1_REG   (3 * AC4)                 // 12288
#define SM1_TOT  (G1_WB + 8 * G1_REG)      // 231424
__global__ __launch_bounds__(512, 1)
void k_gemm_scan(const float* __restrict__ P, const float* __restrict__ Wi,
                 const float* __restrict__ bi, const float* __restrict__ ld_,
                 const float* __restrict__ partIn, float* __restrict__ states)
{
    extern __shared__ float smf[];
    uint32_t sm32 = smem_u32(smf);
    const int tid = threadIdx.x, lane = tid & 31, w = tid >> 5;
    const int grp = w >> 1, nh = w & 1, bid = grp + 1;
    const int lr = lane & 7, lb8 = (lane >> 3) & 1, lb16 = (lane >> 4) & 1;
    const int gid = lane >> 2, tig = lane & 3;
    const int qb = blockIdx.y * 128;

    // persistent W half (128 n-rows x 256 k), pitch 1040B
    {
        int r = tid >> 2, seg = tid & 3;
        const float* s = Wi + (size_t)(qb + r) * 256 + seg * 64;
        uint32_t d = sm32 + r * 1040 + seg * 256;
#pragma unroll
        for (int j = 0; j < 16; j++) cp16(d + j * 16, s + j * 4);
    }
    cp_commit(); cp_wait0();
    __syncthreads();

    const uint32_t AB = sm32 + G1_WB + grp * G1_REG;
    float* ABf = smf + (G1_WB / 4) + grp * (G1_REG / 4);

    for (int tile = blockIdx.x; tile < M_BIG / 256; tile += gridDim.x) {
        const int m0g = tile * 256 + grp * 32;
        const float* Am = P + (size_t)m0g * 256;

        stage_pair(AB,       Am, 0,  nh); cp_commit();
        stage_pair(AB + AC4, Am, 32, nh); cp_commit();

        float acc[2][8][4];
#pragma unroll
        for (int mt = 0; mt < 2; mt++)
#pragma unroll
            for (int j = 0; j < 8; j++)
#pragma unroll
                for (int q = 0; q < 4; q++) acc[mt][j][q] = 0.f;

#pragma unroll 1
        for (int c = 0; c < 8; c++) {
            cp_wait1();
            BARP(bid);
            if (c + 2 < 8) stage_pair(AB + ((c + 2) % 3) * AC4, Am, (c + 2) * 32, nh);
            cp_commit();
            const uint32_t A0 = AB + (c % 3) * AC4;
#pragma unroll
            for (int ks = 0; ks < 4; ks++) {
                const int colb = lb16 * 16 + ks * 32;
                uint32_t a[2][4];
                ldsm4(a[0], A0 + swz(lr + lb8 * 8, colb));
                ldsm4(a[1], A0 + swz(lr + lb8 * 8, colb) + 2048);
#pragma unroll
                for (int ng = 0; ng < 4; ng++) {
                    uint32_t bf[4];
                    ldsm4(bf, sm32 + (nh * 64 + ng * 16 + lr + lb16 * 8) * 1040
                              + lb8 * 16 + (c * 32 + ks * 8) * 4);
                    mma_tf32(acc[0][ng * 2],     a[0], &bf[0]);
                    mma_tf32(acc[0][ng * 2 + 1], a[0], &bf[2]);
                    mma_tf32(acc[1][ng * 2],     a[1], &bf[0]);
                    mma_tf32(acc[1][ng * 2 + 1], a[1], &bf[2]);
                }
            }
        }
        BARP(bid);

        // warp-local epilogue: Uw 16x64 + sc 16 in own slice
        float* Uw = ABf + nh * 1536;
#pragma unroll
        for (int mt = 0; mt < 2; mt++) {
#pragma unroll
            for (int j = 0; j < 8; j++) {
                int col = j * 8 + tig * 2;
                Uw[gid * 64 + col]           = acc[mt][j][0];
                Uw[gid * 64 + col + 1]       = acc[mt][j][1];
                Uw[(gid + 8) * 64 + col]     = acc[mt][j][2];
                Uw[(gid + 8) * 64 + col + 1] = acc[mt][j][3];
            }
            if (lane < 16) Uw[1024 + lane] = part_scale(partIn, m0g + mt * 16 + lane);
            __syncwarp();
#pragma unroll
            for (int q = 0; q < 2; q++) {
                int cc = lane + 32 * q;
                int gc = qb + nh * 64 + cc;
                float dec = 1.0f / (1.0f + expf(-ld_[gc]));
                float bias = bi[gc];
                float st = 0.f;
#pragma unroll
                for (int tt = 0; tt < 16; tt++) {
                    float u = Uw[tt * 64 + cc] * Uw[1024 + tt] + bias;
                    st = dec * st + u;
                    Uw[tt * 64 + cc] = st;
                }
            }
            __syncwarp();
#pragma unroll
            for (int i = 0; i < 8; i++) {
                int f = lane + 32 * i;
                int row = f >> 4, c4 = (f & 15) * 4;
                float4 v = *(float4*)&Uw[row * 64 + c4];
                *(float4*)&states[(size_t)(m0g + mt * 16 + row) * 256
                                  + qb + nh * 64 + c4] = v;
            }
            __syncwarp();
        }
        BARP(bid);
    }
}

// =========== GEMM2: 512 thr, 8 pair-groups, BN=64, K=512 ([Ws;Wo]), 3 A bufs ===========
#define G2_WB    132096
#define G2_REG   (3 * AC4)
#define SM2_TOT  (G2_WB + 8 * G2_REG)      // 230400
__global__ __launch_bounds__(512, 1)
void k_gemm2(const float* __restrict__ P, const float* __restrict__ Wsp,
             const float* __restrict__ states, const float* __restrict__ Wo,
             const float* __restrict__ partIn,
             const float* __restrict__ bo, const float* __restrict__ bsk,
             float* __restrict__ Q, float* __restrict__ partOut)
{
    extern __shared__ float smf[];
    uint32_t sm32 = smem_u32(smf);
    const int tid = threadIdx.x, lane = tid & 31, w = tid >> 5;
    const int grp = w >> 1, nh = w & 1, bid = grp + 1;
    const int lr = lane & 7, lb8 = (lane >> 3) & 1, lb16 = (lane >> 4) & 1;
    const int gid = lane >> 2, tig = lane & 3;
    const int qb = blockIdx.y * 64;

    // persistent [Ws | Wo] quarter (64 n-rows x 512 k), pitch 2064B
    {
        int r = tid >> 3, seg = tid & 7;
        int col64 = seg * 64;
        const float* s = (col64 < 256) ? (Wsp + (size_t)(qb + r) * 256 + col64)
                                       : (Wo  + (size_t)(qb + r) * 256 + col64 - 256);
        uint32_t d = sm32 + r * 2064 + col64 * 4;
#pragma unroll
        for (int j = 0; j < 16; j++) cp16(d + j * 16, s + j * 4);
    }
    cp_commit(); cp_wait0();
    __syncthreads();

    const uint32_t AB = sm32 + G2_WB + grp * G2_REG;
    float* ABf = smf + (G2_WB / 4) + grp * (G2_REG / 4);

    for (int tile = blockIdx.x; tile < M_BIG / 256; tile += gridDim.x) {
        const int m0g = tile * 256 + grp * 32;
        const float* Pm = P + (size_t)m0g * 256;
        const float* Sm = states + (size_t)m0g * 256;

        stage_pair(AB,       Pm, 0,  nh); cp_commit();
        stage_pair(AB + AC4, Pm, 32, nh); cp_commit();

        float acc[2][4][4];
#pragma unroll
        for (int mt = 0; mt < 2; mt++)
#pragma unroll
            for (int j = 0; j < 4; j++)
#pragma unroll
                for (int q = 0; q < 4; q++) acc[mt][j][q] = 0.f;

#pragma unroll 1
        for (int c = 0; c < 16; c++) {
            cp_wait1();
            BARP(bid);
            if (c + 2 < 16) {
                int cn = c + 2;
                stage_pair(AB + (cn % 3) * AC4, cn < 8 ? Pm : Sm, (cn & 7) * 32, nh);
            }
            cp_commit();
            if (c == 8) {
                // finished x@Ws' half: apply rmsnorm row scales to acc
#pragma unroll
                for (int mt = 0; mt < 2; mt++) {
                    float s0 = part_scale(partIn, m0g + mt * 16 + gid);
                    float s1 = part_scale(partIn, m0g + mt * 16 + gid + 8);
#pragma unroll
                    for (int j = 0; j < 4; j++) {
                        acc[mt][j][0] *= s0; acc[mt][j][1] *= s0;
                        acc[mt][j][2] *= s1; acc[mt][j][3] *= s1;
                    }
                }
            }
            const uint32_t A0 = AB + (c % 3) * AC4;
            // batch all A-fragment LDSMs for the chunk (MLP burst)
            uint32_t afr[4][2][4];
#pragma unroll
            for (int ks = 0; ks < 4; ks++) {
                const int colb = lb16 * 16 + ks * 32;
                ldsm4(afr[ks][0], A0 + swz(lr + lb8 * 8, colb));
                ldsm4(afr[ks][1], A0 + swz(lr + lb8 * 8, colb) + 2048);
            }
#pragma unroll
            for (int ks = 0; ks < 4; ks++) {
#pragma unroll
                for (int ng = 0; ng < 2; ng++) {
                    uint32_t bf[4];
                    ldsm4(bf, sm32 + (nh * 32 + ng * 16 + lr + lb16 * 8) * 2064
                              + lb8 * 16 + (c * 32 + ks * 8) * 4);
                    mma_tf32(acc[0][ng * 2],     afr[ks][0], &bf[0]);
                    mma_tf32(acc[0][ng * 2 + 1], afr[ks][0], &bf[2]);
                    mma_tf32(acc[1][ng * 2],     afr[ks][1], &bf[0]);
                    mma_tf32(acc[1][ng * 2 + 1], afr[ks][1], &bf[2]);
                }
            }
        }
        BARP(bid);   // pair done computing before Us overwrites buffers

        // epilogue: Us[32][64] per group
        float* Us = ABf;
#pragma unroll
        for (int mt = 0; mt < 2; mt++) {
            int r = mt * 16 + gid;
#pragma unroll
            for (int j = 0; j < 4; j++) {
                int col = nh * 32 + j * 8 + tig * 2;
                float bb0 = bo[qb + col]     + bsk[qb + col];
                float bb1 = bo[qb + col + 1] + bsk[qb + col + 1];
                Us[r * 64 + col]           = acc[mt][j][0] + bb0;
                Us[r * 64 + col + 1]       = acc[mt][j][1] + bb1;
                Us[(r + 8) * 64 + col]     = acc[mt][j][2] + bb0;
                Us[(r + 8) * 64 + col + 1] = acc[mt][j][3] + bb1;
            }
        }
        BARP(bid);
        // residual + store + per-row partial sumsq over the group's n64
#pragma unroll
        for (int i = 0; i < 8; i++) {
            int f = nh * 32 + lane + 64 * i;
            int row = f >> 4, c4 = (f & 15) * 4;
            float4 v = *(float4*)&Us[row * 64 + c4];
            float4 p = *(const float4*)&Pm[(size_t)row * 256 + qb + c4];
            v.x += p.x; v.y += p.y; v.z += p.z; v.w += p.w;
            *(float4*)&Q[(size_t)(m0g + row) * 256 + qb + c4] = v;
            float s = v.x * v.x + v.y * v.y + v.z * v.z + v.w * v.w;
            s += __shfl_xor_sync(0xffffffffu, s, 1);
            s += __shfl_xor_sync(0xffffffffu, s, 2);
            s += __shfl_xor_sync(0xffffffffu, s, 4);
            s += __shfl_xor_sync(0xffffffffu, s, 8);
            if ((lane & 15) == 0)
                partOut[(size_t)blockIdx.y * M_BIG + m0g + row] = s;
        }
        BARP(bid);
    }
}

// =========== prologue / small kernels ===========
__global__ void prep_weights(const float* __restrict__ Wi, const float* __restrict__ Wo,
                             const float* __restrict__ Wsk, const float* __restrict__ nw,
                             const float* __restrict__ W0)
{
    int i = blockIdx.x * blockDim.x + threadIdx.x;
    if (i < L_ * D_ * D_) {
        int l = i >> 16, k = i & 255;
        float w = nw[l * D_ + k];
        g_Wi[i] = rna(Wi[i] * w);
        g_Ws[i] = rna(Wsk[i] * w);
        g_Wo[i] = rna(Wo[i]);
    }
    if (i < D_ * KIN_) g_W0r[i] = rna(W0[i]);
}

__global__ void shift_scale_kernel(const float* __restrict__ deter,
                                   float* __restrict__ tok, float* __restrict__ part0)
{
    int gw = (blockIdx.x * blockDim.x + threadIdx.x) >> 5;
    if (gw >= B_ * 15) return;
    int lane = threadIdx.x & 31;
    int b = gw / 15, t = gw - b * 15;
    const float4* src = (const float4*)(deter + (size_t)b * 4096 + (t + 1) * 256) + lane;
    float4* dst = (float4*)(tok + (size_t)b * 4096 + t * 256) + lane;
    float4 v0 = src[0], v1 = src[32];
    dst[0] = v0; dst[32] = v1;
    float s = v0.x*v0.x + v0.y*v0.y + v0.z*v0.z + v0.w*v0.w
            + v1.x*v1.x + v1.y*v1.y + v1.z*v1.z + v1.w*v1.w;
#pragma unroll
    for (int o = 16; o > 0; o >>= 1) s += __shfl_xor_sync(0xffffffffu, s, o);
    if (lane == 0) {
        int mm = b * 16 + t;
        part0[mm] = s;
        part0[M_BIG + mm] = 0.f;
        part0[2 * M_BIG + mm] = 0.f;
        part0[3 * M_BIG + mm] = 0.f;
    }
}

__global__ void apply_norm_kernel(const float* __restrict__ in, const float* __restrict__ w,
                                  float* __restrict__ out)
{
    int gw = (blockIdx.x * blockDim.x + threadIdx.x) >> 5;
    int lane = threadIdx.x & 31;
    const float* rp = in + (size_t)gw * 256 + lane * 8;
    float v[8];
    *(float4*)&v[0] = *(const float4*)rp;
    *(float4*)&v[4] = *(const float4*)(rp + 4);
    float s = 0.f;
#pragma unroll
    for (int j = 0; j < 8; j++) s += v[j] * v[j];
#pragma unroll
    for (int o = 16; o > 0; o >>= 1) s += __shfl_xor_sync(0xffffffffu, s, o);
    float sc = rsqrtf(s * (1.0f / 256.0f) + EPS_);
    float wl[8];
    *(float4*)&wl[0] = *(const float4*)(w + lane * 8);
    *(float4*)&wl[4] = *(const float4*)(w + lane * 8 + 4);
    float o8[8];
#pragma unroll
    for (int j = 0; j < 8; j++) o8[j] = v[j] * sc * wl[j];
    float* op = out + (size_t)gw * 256 + lane * 8;
    *(float4*)op = *(float4*)&o8[0];
    *(float4*)(op + 4) = *(float4*)&o8[4];
}

// =========== input proj: BM=32, 128 CTAs, 3 bufs, 1 sync/chunk, fused concat ===========
#define KPB_B    13824
#define SMP_TOT  124416

__device__ __forceinline__ void kp_stageA(uint32_t sm32, int buf,
                                          const float* stoch, int m0, int c)
{
    const int tid = threadIdx.x;
    int row = tid >> 3, kc = (tid & 7) * 4;
    cp16(sm32 + buf * ACHUNK + row * 144 + kc * 4,
         stoch + (size_t)(m0 + row) * 1024 + c * 32 + kc);
}

__device__ __forceinline__ void kp_stageB(uint32_t sm32, int buf, int c)
{
    const int tid = threadIdx.x;
    const float* p = g_W0r + (size_t)tid * KIN_ + c * 32;
    uint32_t d = sm32 + KPB_B + buf * 36864 + tid * 144;
#pragma unroll
    for (int j = 0; j < 8; j++) cp16(d + j * 16, p + j * 4);
}

__global__ __launch_bounds__(256)
void k_proj(const float* __restrict__ stoch, const float* __restrict__ action,
            const float* __restrict__ b0, const float* __restrict__ g0,
            float* __restrict__ tokA, float* __restrict__ part0)
{
    extern __shared__ float smf[];
    uint32_t sm32 = smem_u32(smf);
    const int tid = threadIdx.x, wid = tid >> 5, lane = tid & 31;
    const int wm = wid & 1, wn = wid >> 1;
    const int gid = lane >> 2, tig = lane & 3;
    const int lr = lane & 7, lb8 = (lane >> 3) & 1, lb16 = (lane >> 4) & 1;
    const int m0 = blockIdx.x * 32;

    const uint32_t aoff = (uint32_t)(wm * 16 + lr + lb8 * 8) * 144 + lb16 * 16;
    const uint32_t boff = (uint32_t)(wn * 64 + lr + lb16 * 8) * 144 + lb8 * 16;

    float acc[8][4];
#pragma unroll
    for (int j = 0; j < 8; j++)
#pragma unroll
        for (int q = 0; q < 4; q++) acc[j][q] = 0.f;

    kp_stageA(sm32, 0, stoch, m0, 0); kp_stageB(sm32, 0, 0); cp_commit();
    kp_stageA(sm32, 1, stoch, m0, 1); kp_stageB(sm32, 1, 1); cp_commit();

#pragma unroll 1
    for (int c = 0; c < 33; c++) {
        if (c == 32) cp_wait0(); else cp_wait1();
        __syncthreads();
        int cn = c + 2;
        if (cn < 33) {
            int buf = cn % 3;
            if (cn == 32) {
                int row = tid >> 3, kc = (tid & 7) * 4;
                const float* p = action + (size_t)(m0 + row) * 32 + kc;
                float4 v = *(const float4*)p;
                v.x /= fmaxf(fabsf(v.x), 1.0f);
                v.y /= fmaxf(fabsf(v.y), 1.0f);
                v.z /= fmaxf(fabsf(v.z), 1.0f);
                v.w /= fmaxf(fabsf(v.w), 1.0f);
                *(float4*)((char*)smf + buf * ACHUNK + row * 144 + kc * 4) = v;
                kp_stageB(sm32, buf, cn);
            } else {
                kp_stageA(sm32, buf, stoch, m0, cn);
                kp_stageB(sm32, buf, cn);
            }
        }
        cp_commit();
        const uint32_t sA = sm32 + (c % 3) * ACHUNK;
        const uint32_t sB = sm32 + KPB_B + (c % 3) * 36864;
#pragma unroll
        for (int ks = 0; ks < 4; ks++) {
            uint32_t a0[4], bf[4][4];
            ldsm4(a0, sA + aoff + ks * 32);
#pragma unroll
            for (int pr = 0; pr < 4; pr++)
                ldsm4(bf[pr], sB + boff + pr * 2304 + ks * 32);
#pragma unroll
            for (int pr = 0; pr < 4; pr++) {
                mma_tf32(acc[2*pr],   a0, &bf[pr][0]);
                mma_tf32(acc[2*pr+1], a0, &bf[pr][2]);
            }
        }
    }
    __syncthreads();

    float* Us = smf;   // [32][260]
#pragma unroll
    for (int j = 0; j < 8; j++) {
        int r = wm * 16 + gid;
        int col = wn * 64 + j * 8 + tig * 2;
        Us[r * 260 + col]           = acc[j][0];
        Us[r * 260 + col + 1]       = acc[j][1];
        Us[(r + 8) * 260 + col]     = acc[j][2];
        Us[(r + 8) * 260 + col + 1] = acc[j][3];
    }
    __syncthreads();
#pragma unroll
    for (int k = 0; k < 4; k++) {
        int row = k * 8 + wid;
        int m = m0 + row;
        float v[8]; float sum = 0.f;
#pragma unroll
        for (int j = 0; j < 8; j++) {
            int c = lane + 32 * j;
            v[j] = Us[row * 260 + c] + b0[c];
            sum += v[j] * v[j];
        }
#pragma unroll
        for (int o = 16; o > 0; o >>= 1) sum += __shfl_xor_sync(0xffffffffu, sum, o);
        float sc = rsqrtf(sum * (1.0f / 256.0f) + EPS_);
        float s2 = 0.f;
#pragma unroll
        for (int j = 0; j < 8; j++) {
            int c = lane + 32 * j;
            float y = v[j] * sc * g0[c];
            y = y / (1.0f + expf(-y));
            s2 += y * y;
            tokA[(size_t)m * 4096 + 3840 + c] = y;
        }
#pragma unroll
        for (int o = 16; o > 0; o >>= 1) s2 += __shfl_xor_sync(0xffffffffu, s2, o);
        if (lane == 0) {
            int mm = m * 16 + 15;
            part0[mm] = s2;
            part0[M_BIG + mm] = 0.f;
            part0[2 * M_BIG + mm] = 0.f;
            part0[3 * M_BIG + mm] = 0.f;
        }
    }
}

// ---------------- launch ----------------
extern "C" void kernel_launch(void* const* d_in, const int* in_sizes, int n_in,
                              void* d_out, int out_size)
{
    const float* stoch      = (const float*)d_in[0];
    const float* deter      = (const float*)d_in[1];
    const float* action     = (const float*)d_in[2];
    const float* W0         = (const float*)d_in[3];
    const float* b0         = (const float*)d_in[4];
    const float* g0         = (const float*)d_in[5];
    const float* norm_w     = (const float*)d_in[6];
    const float* W_in       = (const float*)d_in[7];
    const float* b_in       = (const float*)d_in[8];
    const float* W_out      = (const float*)d_in[9];
    const float* b_out      = (const float*)d_in[10];
    const float* W_skip     = (const float*)d_in[11];
    const float* b_skip     = (const float*)d_in[12];
    const float* log_decay  = (const float*)d_in[13];
    const float* out_norm_w = (const float*)d_in[14];
    float* out = (float*)d_out;

    float *tokA, *tokB, *states, *part, *Wi_s, *Wo_s, *Ws_s;
    cudaGetSymbolAddress((void**)&tokA,   g_tokA);
    cudaGetSymbolAddress((void**)&tokB,   g_tokB);
    cudaGetSymbolAddress((void**)&states, g_states);
    cudaGetSymbolAddress((void**)&part,   g_part);
    cudaGetSymbolAddress((void**)&Wi_s,   g_Wi);
    cudaGetSymbolAddress((void**)&Wo_s,   g_Wo);
    cudaGetSymbolAddress((void**)&Ws_s,   g_Ws);

    cudaFuncSetAttribute(k_proj,      cudaFuncAttributeMaxDynamicSharedMemorySize, SMP_TOT);
    cudaFuncSetAttribute(k_gemm_scan, cudaFuncAttributeMaxDynamicSharedMemorySize, SM1_TOT);
    cudaFuncSetAttribute(k_gemm2,     cudaFuncAttributeMaxDynamicSharedMemorySize, SM2_TOT);

    prep_weights<<<(D_ * KIN_ + 255) / 256 + 1, 256>>>(W_in, W_out, W_skip, norm_w, W0);
    shift_scale_kernel<<<B_ * 15 / 8, 256>>>(deter, tokA, part);
    k_proj<<<B_ / 32, 256, SMP_TOT>>>(stoch, action, b0, g0, tokA, part);

    float* Pb = tokA;
    float* Qb = tokB;
    for (int l = 0; l < L_; l++) {
        const float* Wi  = Wi_s + (size_t)l * D_ * D_;
        const float* Wo  = Wo_s + (size_t)l * D_ * D_;
        const float* Ws  = Ws_s + (size_t)l * D_ * D_;
        const float* bi  = b_in      + (size_t)l * D_;
        const float* bo  = b_out     + (size_t)l * D_;
        const float* bsk = b_skip    + (size_t)l * D_;
        const float* ld  = log_decay + (size_t)l * D_;
        float* partIn  = part + (size_t)(l & 1) * 4 * M_BIG;
        float* partOut = part + (size_t)((l + 1) & 1) * 4 * M_BIG;

        k_gemm_scan<<<dim3(74, 2), 512, SM1_TOT>>>(Pb, Wi, bi, ld, partIn, states);
        k_gemm2<<<dim3(37, 4), 512, SM2_TOT>>>(Pb, Ws, states, Wo, partIn,
                                               bo, bsk, Qb, partOut);
        float* tmp = Pb; Pb = Qb; Qb = tmp;
    }

    apply_norm_kernel<<<M_BIG / 8, 256>>>(Pb, out_norm_w, out);
}